// round 13
// baseline (speedup 1.0000x reference)
#include <cuda_runtime.h>
#include <cstdint>

// Counting-sort edges by src, then process 4 sorted edges per 16-lane group
// with a dedupe fast path: when all 4 share src (likely: ~20 edges/node),
// G[src],K[src],V[src] load ONCE per group (11 gathers instead of 20),
// cutting L1tex read wavefronts ~37%. Sort kernels: zero/hist/scan/scatter.
// Scatter order within a bin is nondeterministic but output is per-edge, so
// results are deterministic. Main kernel: folding butterfly reduction,
// epilogue once per warp, L2 evict_last gathers, streaming stores.

#define MAX_EDGES 1000000
#define MAX_NODES 50176

__device__ int  g_cnt[MAX_NODES];
__device__ int  g_off[MAX_NODES];
__device__ int4 g_rec[MAX_EDGES];   // (edge_id, src, dst, 0) sorted by src

__global__ void zero_kernel(int n_nodes) {
    int i = blockIdx.x * blockDim.x + threadIdx.x;
    if (i < n_nodes) g_cnt[i] = 0;
}

__global__ void hist_kernel(const int* __restrict__ src, int n_edges, int n_nodes) {
    int e = blockIdx.x * blockDim.x + threadIdx.x;
    if (e < n_edges) {
        int s = min(max(src[e], 0), n_nodes - 1);
        atomicAdd(&g_cnt[s], 1);
    }
}

// Single-block exclusive scan of g_cnt[0..n_nodes) into g_off.
__global__ void scan_kernel(int n_nodes) {
    __shared__ int sm[1024];
    int t = threadIdx.x;
    int chunk = (n_nodes + 1023) >> 10;
    int b = t * chunk;
    int e = min(b + chunk, n_nodes);
    int sum = 0;
    for (int i = b; i < e; i++) sum += g_cnt[i];
    sm[t] = sum;
    __syncthreads();
    for (int off = 1; off < 1024; off <<= 1) {
        int v = (t >= off) ? sm[t - off] : 0;
        __syncthreads();
        sm[t] += v;
        __syncthreads();
    }
    int run = (t == 0) ? 0 : sm[t - 1];
    for (int i = b; i < e; i++) { int c = g_cnt[i]; g_off[i] = run; run += c; }
}

__global__ void scatter_kernel(const int* __restrict__ src,
                               const int* __restrict__ dst,
                               int n_edges, int n_nodes) {
    int e = blockIdx.x * blockDim.x + threadIdx.x;
    if (e < n_edges) {
        int s = min(max(src[e], 0), n_nodes - 1);
        int d = min(max(dst[e], 0), n_nodes - 1);
        int pos = atomicAdd(&g_off[s], 1);
        g_rec[pos] = make_int4(e, s, d, 0);
    }
}

__device__ __forceinline__ float4 ldg_el(const float* p, uint64_t pol) {
    float4 v;
    asm volatile(
        "ld.global.nc.L2::cache_hint.v4.f32 {%0,%1,%2,%3}, [%4], %5;"
        : "=f"(v.x), "=f"(v.y), "=f"(v.z), "=f"(v.w)
        : "l"(p), "l"(pol));
    return v;
}

#define SHX(v, off) __shfl_xor_sync(0xFFFFFFFFu, (v), (off), 16)

__global__ void __launch_bounds__(128, 10) rpm_main(
    const float* __restrict__ G,
    const float* __restrict__ K,
    const float* __restrict__ Q,
    const float* __restrict__ V,
    float* __restrict__ out,
    int n_edges)
{
    uint64_t pol;
    asm("createpolicy.fractional.L2::evict_last.b64 %0, 1.0;" : "=l"(pol));

    int sub  = threadIdx.x >> 4;
    int lane = threadIdx.x & 15;
    int g    = blockIdx.x * (blockDim.x >> 4) + sub;
    int p0   = g * 4;

    // 4 sorted records (uniform across the 16 lanes; clamp for tail, no early
    // return so warp-wide shfl masks stay legal).
    int4 r0 = g_rec[min(p0 + 0, n_edges - 1)];
    int4 r1 = g_rec[min(p0 + 1, n_edges - 1)];
    int4 r2 = g_rec[min(p0 + 2, n_edges - 1)];
    int4 r3 = g_rec[min(p0 + 3, n_edges - 1)];

    size_t l4 = (size_t)lane * 4;

    float4 vs0, vs1, vs2, vs3;
    float pd0, pk0, pd1, pk1, pd2, pk2, pd3, pk3;
    float dx, dy, dz, dw;

    if (r0.y == r1.y && r1.y == r2.y && r2.y == r3.y) {
        // ---- fast path: shared src → 3 src gathers + 8 dst gathers ----
        float4 gs = ldg_el(G + (size_t)r0.y * 64 + l4, pol);
        float4 ks = ldg_el(K + (size_t)r0.y * 64 + l4, pol);
        float4 vs = ldg_el(V + (size_t)r0.y * 64 + l4, pol);
        float4 gd0 = ldg_el(G + (size_t)r0.z * 64 + l4, pol);
        float4 qd0 = ldg_el(Q + (size_t)r0.z * 64 + l4, pol);
        float4 gd1 = ldg_el(G + (size_t)r1.z * 64 + l4, pol);
        float4 qd1 = ldg_el(Q + (size_t)r1.z * 64 + l4, pol);
        float4 gd2 = ldg_el(G + (size_t)r2.z * 64 + l4, pol);
        float4 qd2 = ldg_el(Q + (size_t)r2.z * 64 + l4, pol);
        float4 gd3 = ldg_el(G + (size_t)r3.z * 64 + l4, pol);
        float4 qd3 = ldg_el(Q + (size_t)r3.z * 64 + l4, pol);

        dx = gs.x-gd0.x; dy = gs.y-gd0.y; dz = gs.z-gd0.z; dw = gs.w-gd0.w;
        pd0 = dx*dx + dy*dy + dz*dz + dw*dw;
        pk0 = ks.x*qd0.x + ks.y*qd0.y + ks.z*qd0.z + ks.w*qd0.w;
        dx = gs.x-gd1.x; dy = gs.y-gd1.y; dz = gs.z-gd1.z; dw = gs.w-gd1.w;
        pd1 = dx*dx + dy*dy + dz*dz + dw*dw;
        pk1 = ks.x*qd1.x + ks.y*qd1.y + ks.z*qd1.z + ks.w*qd1.w;
        dx = gs.x-gd2.x; dy = gs.y-gd2.y; dz = gs.z-gd2.z; dw = gs.w-gd2.w;
        pd2 = dx*dx + dy*dy + dz*dz + dw*dw;
        pk2 = ks.x*qd2.x + ks.y*qd2.y + ks.z*qd2.z + ks.w*qd2.w;
        dx = gs.x-gd3.x; dy = gs.y-gd3.y; dz = gs.z-gd3.z; dw = gs.w-gd3.w;
        pd3 = dx*dx + dy*dy + dz*dz + dw*dw;
        pk3 = ks.x*qd3.x + ks.y*qd3.y + ks.z*qd3.z + ks.w*qd3.w;
        vs0 = vs; vs1 = vs; vs2 = vs; vs3 = vs;
    } else {
        // ---- general path: per-edge src (R9 structure) ----
        float4 gs0 = ldg_el(G + (size_t)r0.y * 64 + l4, pol);
        float4 gd0 = ldg_el(G + (size_t)r0.z * 64 + l4, pol);
        float4 ks0 = ldg_el(K + (size_t)r0.y * 64 + l4, pol);
        float4 qd0 = ldg_el(Q + (size_t)r0.z * 64 + l4, pol);
        vs0        = ldg_el(V + (size_t)r0.y * 64 + l4, pol);
        float4 gs1 = ldg_el(G + (size_t)r1.y * 64 + l4, pol);
        float4 gd1 = ldg_el(G + (size_t)r1.z * 64 + l4, pol);
        float4 ks1 = ldg_el(K + (size_t)r1.y * 64 + l4, pol);
        float4 qd1 = ldg_el(Q + (size_t)r1.z * 64 + l4, pol);
        vs1        = ldg_el(V + (size_t)r1.y * 64 + l4, pol);
        float4 gs2 = ldg_el(G + (size_t)r2.y * 64 + l4, pol);
        float4 gd2 = ldg_el(G + (size_t)r2.z * 64 + l4, pol);
        float4 ks2 = ldg_el(K + (size_t)r2.y * 64 + l4, pol);
        float4 qd2 = ldg_el(Q + (size_t)r2.z * 64 + l4, pol);
        vs2        = ldg_el(V + (size_t)r2.y * 64 + l4, pol);
        float4 gs3 = ldg_el(G + (size_t)r3.y * 64 + l4, pol);
        float4 gd3 = ldg_el(G + (size_t)r3.z * 64 + l4, pol);
        float4 ks3 = ldg_el(K + (size_t)r3.y * 64 + l4, pol);
        float4 qd3 = ldg_el(Q + (size_t)r3.z * 64 + l4, pol);
        vs3        = ldg_el(V + (size_t)r3.y * 64 + l4, pol);

        dx = gs0.x-gd0.x; dy = gs0.y-gd0.y; dz = gs0.z-gd0.z; dw = gs0.w-gd0.w;
        pd0 = dx*dx + dy*dy + dz*dz + dw*dw;
        pk0 = ks0.x*qd0.x + ks0.y*qd0.y + ks0.z*qd0.z + ks0.w*qd0.w;
        dx = gs1.x-gd1.x; dy = gs1.y-gd1.y; dz = gs1.z-gd1.z; dw = gs1.w-gd1.w;
        pd1 = dx*dx + dy*dy + dz*dz + dw*dw;
        pk1 = ks1.x*qd1.x + ks1.y*qd1.y + ks1.z*qd1.z + ks1.w*qd1.w;
        dx = gs2.x-gd2.x; dy = gs2.y-gd2.y; dz = gs2.z-gd2.z; dw = gs2.w-gd2.w;
        pd2 = dx*dx + dy*dy + dz*dz + dw*dw;
        pk2 = ks2.x*qd2.x + ks2.y*qd2.y + ks2.z*qd2.z + ks2.w*qd2.w;
        dx = gs3.x-gd3.x; dy = gs3.y-gd3.y; dz = gs3.z-gd3.z; dw = gs3.w-gd3.w;
        pd3 = dx*dx + dy*dy + dz*dz + dw*dw;
        pk3 = ks3.x*qd3.x + ks3.y*qd3.y + ks3.z*qd3.z + ks3.w*qd3.w;
    }

    // ---- folding reduction: 8 values over 16 lanes (R9-proven) ----
    pd0 += SHX(pd0, 8);  pk0 += SHX(pk0, 8);
    pd1 += SHX(pd1, 8);  pk1 += SHX(pk1, 8);
    pd2 += SHX(pd2, 8);  pk2 += SHX(pk2, 8);
    pd3 += SHX(pd3, 8);  pk3 += SHX(pk3, 8);
    bool h8 = (lane & 8) != 0;
    float y0 = h8 ? pk0 : pd0;
    float y1 = h8 ? pk1 : pd1;
    float y2 = h8 ? pk2 : pd2;
    float y3 = h8 ? pk3 : pd3;
    y0 += SHX(y0, 4);  y1 += SHX(y1, 4);  y2 += SHX(y2, 4);  y3 += SHX(y3, 4);
    bool h4 = (lane & 4) != 0;
    float z0 = h4 ? y1 : y0;
    float z1 = h4 ? y3 : y2;
    z0 += SHX(z0, 2);  z1 += SHX(z1, 2);
    bool h2 = (lane & 2) != 0;
    float u = h2 ? z1 : z0;
    u += SHX(u, 1);
    float t = SHX(u, 8);
    float pdv = h8 ? t : u;
    float pkv = h8 ? u : t;

    const float isd = 0.125f;  // 1/sqrt(64)
    float a = fminf(fmaxf(-sqrtf(pdv + 1e-6f) * isd, -5.0f), 5.0f);
    float b = fminf(fmaxf(pkv * isd, -5.0f), 5.0f);
    float w = __expf(a + b);

    float w0 = __shfl_sync(0xFFFFFFFFu, w, 0, 16);
    float w1 = __shfl_sync(0xFFFFFFFFu, w, 4, 16);
    float w2 = __shfl_sync(0xFFFFFFFFu, w, 2, 16);
    float w3 = __shfl_sync(0xFFFFFFFFu, w, 6, 16);

    float4* out4 = reinterpret_cast<float4*>(out);
    if (p0 + 0 < n_edges)
        __stcs(&out4[(size_t)r0.x * 16 + lane],
               make_float4(w0*vs0.x, w0*vs0.y, w0*vs0.z, w0*vs0.w));
    if (p0 + 1 < n_edges)
        __stcs(&out4[(size_t)r1.x * 16 + lane],
               make_float4(w1*vs1.x, w1*vs1.y, w1*vs1.z, w1*vs1.w));
    if (p0 + 2 < n_edges)
        __stcs(&out4[(size_t)r2.x * 16 + lane],
               make_float4(w2*vs2.x, w2*vs2.y, w2*vs2.z, w2*vs2.w));
    if (p0 + 3 < n_edges)
        __stcs(&out4[(size_t)r3.x * 16 + lane],
               make_float4(w3*vs3.x, w3*vs3.y, w3*vs3.z, w3*vs3.w));
}

// Fallback (R9, no sort) if sizes exceed static scratch.
__global__ void __launch_bounds__(128, 12) rpm_fallback(
    const float* __restrict__ G, const float* __restrict__ K,
    const float* __restrict__ Q, const float* __restrict__ V,
    const int* __restrict__ src, const int* __restrict__ dst,
    float* __restrict__ out, int n_edges, int n_nodes)
{
    uint64_t pol;
    asm("createpolicy.fractional.L2::evict_last.b64 %0, 1.0;" : "=l"(pol));
    int sub  = threadIdx.x >> 4;
    int lane = threadIdx.x & 15;
    int g    = blockIdx.x * (blockDim.x >> 4) + sub;
    int e    = min(g, n_edges - 1);
    bool live = (g < n_edges);
    int s = min(max(src[e], 0), n_nodes - 1);
    int d = min(max(dst[e], 0), n_nodes - 1);
    size_t l4 = (size_t)lane * 4;
    float4 gs = ldg_el(G + (size_t)s * 64 + l4, pol);
    float4 gd = ldg_el(G + (size_t)d * 64 + l4, pol);
    float4 ks = ldg_el(K + (size_t)s * 64 + l4, pol);
    float4 qd = ldg_el(Q + (size_t)d * 64 + l4, pol);
    float4 vs = ldg_el(V + (size_t)s * 64 + l4, pol);
    float dx = gs.x-gd.x, dy = gs.y-gd.y, dz = gs.z-gd.z, dw = gs.w-gd.w;
    float pd = dx*dx + dy*dy + dz*dz + dw*dw;
    float pk = ks.x*qd.x + ks.y*qd.y + ks.z*qd.z + ks.w*qd.w;
    #pragma unroll
    for (int off = 8; off > 0; off >>= 1) {
        pd += SHX(pd, off);
        pk += SHX(pk, off);
    }
    const float isd = 0.125f;
    float a = fminf(fmaxf(-sqrtf(pd + 1e-6f) * isd, -5.0f), 5.0f);
    float b = fminf(fmaxf(pk * isd, -5.0f), 5.0f);
    float w = __expf(a + b);
    if (live)
        __stcs(&reinterpret_cast<float4*>(out)[(size_t)e * 16 + lane],
               make_float4(w*vs.x, w*vs.y, w*vs.z, w*vs.w));
}

extern "C" void kernel_launch(void* const* d_in, const int* in_sizes, int n_in,
                              void* d_out, int out_size) {
    const float* G = (const float*)d_in[0];
    const float* K = (const float*)d_in[1];
    const float* Q = (const float*)d_in[2];
    const float* V = (const float*)d_in[3];
    const int* src = (const int*)d_in[4];
    const int* dst = (const int*)d_in[5];
    float* out = (float*)d_out;

    int n_edges = in_sizes[4];
    int n_nodes = in_sizes[0] / 64;

    if (n_edges > MAX_EDGES || n_nodes > MAX_NODES) {
        int groups_per_block = 128 / 16;
        int blocks = (n_edges + groups_per_block - 1) / groups_per_block;
        rpm_fallback<<<blocks, 128>>>(G, K, Q, V, src, dst, out, n_edges, n_nodes);
        return;
    }

    zero_kernel<<<(n_nodes + 255) / 256, 256>>>(n_nodes);
    hist_kernel<<<(n_edges + 255) / 256, 256>>>(src, n_edges, n_nodes);
    scan_kernel<<<1, 1024>>>(n_nodes);
    scatter_kernel<<<(n_edges + 255) / 256, 256>>>(src, dst, n_edges, n_nodes);

    int groups = (n_edges + 3) / 4;
    int blocks = (groups + 7) / 8;     // 8 groups per 128-thread block
    rpm_main<<<blocks, 128>>>(G, K, Q, V, out, n_edges);
}

// round 14
// speedup vs baseline: 2.0506x; 2.0506x over previous
#include <cuda_runtime.h>
#include <cstdint>

// R9 (proven best: 79.9us): 128-thread CTAs, launch_bounds(128,12) -> regs=40
// sweet spot, 48-warp/SM ceiling. 16 lanes/group, float4/lane, 4 edges/group,
// 20 gathers batched, folding butterfly reduction, epilogue once per warp.
// Delta vs R9: gather asm is NON-volatile so ptxas may interleave loads with
// consuming math (better issue scheduling at identical MLP ceiling).
// Gathers: L2 evict_last. Output: evict-first streaming stores.

__device__ __forceinline__ float4 ldg_el(const float* p, uint64_t pol) {
    float4 v;
    asm("ld.global.nc.L2::cache_hint.v4.f32 {%0,%1,%2,%3}, [%4], %5;"
        : "=f"(v.x), "=f"(v.y), "=f"(v.z), "=f"(v.w)
        : "l"(p), "l"(pol));
    return v;
}

#define SHX(v, off) __shfl_xor_sync(0xFFFFFFFFu, (v), (off), 16)

__global__ void __launch_bounds__(128, 12) rpm_kernel(
    const float* __restrict__ G,
    const float* __restrict__ K,
    const float* __restrict__ Q,
    const float* __restrict__ V,
    const int* __restrict__ src,
    const int* __restrict__ dst,
    float* __restrict__ out,
    int n_edges,
    int n_nodes)
{
    uint64_t pol;
    asm("createpolicy.fractional.L2::evict_last.b64 %0, 1.0;" : "=l"(pol));

    int sub  = threadIdx.x >> 4;
    int lane = threadIdx.x & 15;
    int g    = blockIdx.x * (blockDim.x >> 4) + sub;
    int ebase = g * 4;

    int4 s4, d4;
    if (ebase + 3 < n_edges) {
        s4 = reinterpret_cast<const int4*>(src)[g];
        d4 = reinterpret_cast<const int4*>(dst)[g];
    } else {
        int ec0 = min(ebase + 0, n_edges - 1);
        int ec1 = min(ebase + 1, n_edges - 1);
        int ec2 = min(ebase + 2, n_edges - 1);
        int ec3 = min(ebase + 3, n_edges - 1);
        s4 = make_int4(src[ec0], src[ec1], src[ec2], src[ec3]);
        d4 = make_int4(dst[ec0], dst[ec1], dst[ec2], dst[ec3]);
    }

    size_t l4 = (size_t)lane * 4;

    // 20 batched gathers (R9 order).
    float4 gs0 = ldg_el(G + (size_t)s4.x * 64 + l4, pol);
    float4 gd0 = ldg_el(G + (size_t)d4.x * 64 + l4, pol);
    float4 ks0 = ldg_el(K + (size_t)s4.x * 64 + l4, pol);
    float4 qd0 = ldg_el(Q + (size_t)d4.x * 64 + l4, pol);
    float4 vs0 = ldg_el(V + (size_t)s4.x * 64 + l4, pol);
    float4 gs1 = ldg_el(G + (size_t)s4.y * 64 + l4, pol);
    float4 gd1 = ldg_el(G + (size_t)d4.y * 64 + l4, pol);
    float4 ks1 = ldg_el(K + (size_t)s4.y * 64 + l4, pol);
    float4 qd1 = ldg_el(Q + (size_t)d4.y * 64 + l4, pol);
    float4 vs1 = ldg_el(V + (size_t)s4.y * 64 + l4, pol);
    float4 gs2 = ldg_el(G + (size_t)s4.z * 64 + l4, pol);
    float4 gd2 = ldg_el(G + (size_t)d4.z * 64 + l4, pol);
    float4 ks2 = ldg_el(K + (size_t)s4.z * 64 + l4, pol);
    float4 qd2 = ldg_el(Q + (size_t)d4.z * 64 + l4, pol);
    float4 vs2 = ldg_el(V + (size_t)s4.z * 64 + l4, pol);
    float4 gs3 = ldg_el(G + (size_t)s4.w * 64 + l4, pol);
    float4 gd3 = ldg_el(G + (size_t)d4.w * 64 + l4, pol);
    float4 ks3 = ldg_el(K + (size_t)s4.w * 64 + l4, pol);
    float4 qd3 = ldg_el(Q + (size_t)d4.w * 64 + l4, pol);
    float4 vs3 = ldg_el(V + (size_t)s4.w * 64 + l4, pol);

    float dx, dy, dz, dw;
    dx = gs0.x-gd0.x; dy = gs0.y-gd0.y; dz = gs0.z-gd0.z; dw = gs0.w-gd0.w;
    float pd0 = dx*dx + dy*dy + dz*dz + dw*dw;
    float pk0 = ks0.x*qd0.x + ks0.y*qd0.y + ks0.z*qd0.z + ks0.w*qd0.w;
    dx = gs1.x-gd1.x; dy = gs1.y-gd1.y; dz = gs1.z-gd1.z; dw = gs1.w-gd1.w;
    float pd1 = dx*dx + dy*dy + dz*dz + dw*dw;
    float pk1 = ks1.x*qd1.x + ks1.y*qd1.y + ks1.z*qd1.z + ks1.w*qd1.w;
    dx = gs2.x-gd2.x; dy = gs2.y-gd2.y; dz = gs2.z-gd2.z; dw = gs2.w-gd2.w;
    float pd2 = dx*dx + dy*dy + dz*dz + dw*dw;
    float pk2 = ks2.x*qd2.x + ks2.y*qd2.y + ks2.z*qd2.z + ks2.w*qd2.w;
    dx = gs3.x-gd3.x; dy = gs3.y-gd3.y; dz = gs3.z-gd3.z; dw = gs3.w-gd3.w;
    float pd3 = dx*dx + dy*dy + dz*dz + dw*dw;
    float pk3 = ks3.x*qd3.x + ks3.y*qd3.y + ks3.z*qd3.z + ks3.w*qd3.w;

    // ---- folding reduction: 8 values over 16 lanes ----
    pd0 += SHX(pd0, 8);  pk0 += SHX(pk0, 8);
    pd1 += SHX(pd1, 8);  pk1 += SHX(pk1, 8);
    pd2 += SHX(pd2, 8);  pk2 += SHX(pk2, 8);
    pd3 += SHX(pd3, 8);  pk3 += SHX(pk3, 8);
    bool h8 = (lane & 8) != 0;
    float y0 = h8 ? pk0 : pd0;
    float y1 = h8 ? pk1 : pd1;
    float y2 = h8 ? pk2 : pd2;
    float y3 = h8 ? pk3 : pd3;
    y0 += SHX(y0, 4);  y1 += SHX(y1, 4);  y2 += SHX(y2, 4);  y3 += SHX(y3, 4);
    bool h4 = (lane & 4) != 0;
    float z0 = h4 ? y1 : y0;
    float z1 = h4 ? y3 : y2;
    z0 += SHX(z0, 2);  z1 += SHX(z1, 2);
    bool h2 = (lane & 2) != 0;
    float u = h2 ? z1 : z0;
    u += SHX(u, 1);
    float t = SHX(u, 8);
    float pdv = h8 ? t : u;
    float pkv = h8 ? u : t;

    const float isd = 0.125f;  // 1/sqrt(64)
    float a = fminf(fmaxf(-sqrtf(pdv + 1e-6f) * isd, -5.0f), 5.0f);
    float b = fminf(fmaxf(pkv * isd, -5.0f), 5.0f);
    float w = __expf(a + b);

    float w0 = __shfl_sync(0xFFFFFFFFu, w, 0, 16);
    float w1 = __shfl_sync(0xFFFFFFFFu, w, 4, 16);
    float w2 = __shfl_sync(0xFFFFFFFFu, w, 2, 16);
    float w3 = __shfl_sync(0xFFFFFFFFu, w, 6, 16);

    float4* out4 = reinterpret_cast<float4*>(out);
    if (ebase + 0 < n_edges)
        __stcs(&out4[(size_t)(ebase + 0) * 16 + lane],
               make_float4(w0*vs0.x, w0*vs0.y, w0*vs0.z, w0*vs0.w));
    if (ebase + 1 < n_edges)
        __stcs(&out4[(size_t)(ebase + 1) * 16 + lane],
               make_float4(w1*vs1.x, w1*vs1.y, w1*vs1.z, w1*vs1.w));
    if (ebase + 2 < n_edges)
        __stcs(&out4[(size_t)(ebase + 2) * 16 + lane],
               make_float4(w2*vs2.x, w2*vs2.y, w2*vs2.z, w2*vs2.w));
    if (ebase + 3 < n_edges)
        __stcs(&out4[(size_t)(ebase + 3) * 16 + lane],
               make_float4(w3*vs3.x, w3*vs3.y, w3*vs3.z, w3*vs3.w));
}

extern "C" void kernel_launch(void* const* d_in, const int* in_sizes, int n_in,
                              void* d_out, int out_size) {
    const float* G = (const float*)d_in[0];
    const float* K = (const float*)d_in[1];
    const float* Q = (const float*)d_in[2];
    const float* V = (const float*)d_in[3];
    const int* src = (const int*)d_in[4];
    const int* dst = (const int*)d_in[5];
    float* out = (float*)d_out;

    int n_edges = in_sizes[4];
    int n_nodes = in_sizes[0] / 64;
    int groups_per_block = 128 / 16;              // 8 groups
    int edges_per_block = groups_per_block * 4;   // 32 edges/block
    int blocks = (n_edges + edges_per_block - 1) / edges_per_block;
    rpm_kernel<<<blocks, 128>>>(G, K, Q, V, src, dst, out, n_edges, n_nodes);
}